// round 11
// baseline (speedup 1.0000x reference)
#include <cuda_runtime.h>
#include <cstdint>

// VanillaRNN on GB300 — Round 9: R8 tiling + ks-level fragment double-buffer.
//
//   new_state = ReLU(X@W_in^T + state@W_rec^T + b_in + b_rec)  [8192,4096]
//   out       = ReLU(new_state@W_out^T + b_out)                [8192,1024]
// d_out = (out, new_state); new_state region reused as GEMM3 input.
//
// BM=128, BN=256, BK=32, 256 threads (8 warps, 2x4), warp tile 64x64.
// 3-stage cp.async pipeline (stage 54KB -> 1 CTA/SM, reg ceiling 255).
// Fragments via ldmatrix.m8n8.x4.b16, DOUBLE-BUFFERED across k8 steps:
// LDSM for ks+1 issues before the 32 MMAs of ks, so tensor stays fed.
// tf32-RN rounding (+0x1000) in place. (R6 showed this spills at 184-reg
// ceiling; at 1 CTA/SM the 255 ceiling fits ~210 live regs.)

#define BM 128
#define BN 256
#define BK 32
#define STAGES 3
#define SROW 36                           // floats per smem row (32 + 4 pad)
#define A_FLOATS (BM * SROW)              // 4608
#define B_FLOATS (BN * SROW)              // 9216
#define STAGE_FLOATS (A_FLOATS + B_FLOATS)  // 13824
#define STAGE_BYTES  (STAGE_FLOATS * 4)     // 55296
#define SMEM_BYTES   (STAGES * STAGE_BYTES) // 165888

__device__ __forceinline__ uint32_t s2u(const void* p) {
    uint32_t a;
    asm("{ .reg .u64 t; cvta.to.shared.u64 t, %1; cvt.u32.u64 %0, t; }" : "=r"(a) : "l"(p));
    return a;
}

#define CP16(dst, src) \
    asm volatile("cp.async.cg.shared.global [%0], [%1], 16;" :: "r"(dst), "l"(src))
#define CP_COMMIT() asm volatile("cp.async.commit_group;" ::: "memory")
#define CP_WAIT(N)  asm volatile("cp.async.wait_group %0;" :: "n"(N) : "memory")

#define LDSM4(r0, r1, r2, r3, addr)                                            \
    asm volatile("ldmatrix.sync.aligned.m8n8.x4.shared.b16 {%0,%1,%2,%3}, [%4];" \
                 : "=r"(r0), "=r"(r1), "=r"(r2), "=r"(r3) : "r"(addr))

#define MMA_TF32(ac, a0, a1, a2, a3, b0, b1)                                   \
    asm volatile(                                                              \
        "mma.sync.aligned.m16n8k8.row.col.f32.tf32.tf32.f32 "                  \
        "{%0,%1,%2,%3}, {%4,%5,%6,%7}, {%8,%9}, {%0,%1,%2,%3};"                \
        : "+f"((ac)[0]), "+f"((ac)[1]), "+f"((ac)[2]), "+f"((ac)[3])           \
        : "r"(a0), "r"(a1), "r"(a2), "r"(a3), "r"(b0), "r"(b1))

__global__ void __launch_bounds__(256) rnn_gemm_mma(
    const float* __restrict__ A1, int lda1,
    const float* __restrict__ B1, int ldb1, int n1,
    const float* __restrict__ A2, int lda2,
    const float* __restrict__ B2, int ldb2, int n2,
    const float* __restrict__ bias1, const float* __restrict__ bias2,
    float* __restrict__ C, int ldc)
{
    extern __shared__ __align__(16) float smem[];
    const uint32_t sbase = s2u(smem);

    const int tid  = threadIdx.x;
    const int warp = tid >> 5;
    const int lane = tid & 31;
    const int tg   = lane & 3;    // thread in group (0..3)
    const int g    = lane >> 2;   // group id (0..7)
    const int wm   = warp >> 2;   // warp m index (0..1), rows wm*64..+64
    const int wn   = warp & 3;    // warp n index (0..3), cols wn*64..+64

    const int rowBase = blockIdx.y * BM;
    const int colBase = blockIdx.x * BN;
    const int niters  = n1 + n2;

    // ldmatrix lane offset: lanes 0-15 -> rows 0..15; lanes 16-31 -> +4 fp32 cols
    const uint32_t laneOff = (((uint32_t)(lane & 15)) * SROW + ((lane >> 4) << 2)) * 4;

    float acc[4][8][4];
#pragma unroll
    for (int i = 0; i < 4; i++)
#pragma unroll
        for (int j = 0; j < 8; j++)
#pragma unroll
            for (int v = 0; v < 4; v++) acc[i][j][v] = 0.0f;

    // ---- stage loader: 384 rows (128 A + 256 B), 256 threads, 12 CP16 each
    auto load_stage = [&](int j, int s) {
        const float* Ab; const float* Bb; int lda, ldb, ko;
        if (j < n1) { Ab = A1; Bb = B1; lda = lda1; ldb = ldb1; ko = j * BK; }
        else        { Ab = A2; Bb = B2; lda = lda2; ldb = ldb2; ko = (j - n1) * BK; }
        const uint32_t base = sbase + s * STAGE_BYTES;

        // pass 1: full row per thread. tid<128 -> A row tid; else B row tid-128
        {
            const int r = tid & 127;
            const bool isB = tid >= 128;
            const float* gsrc = isB ? (Bb + (size_t)(colBase + r) * ldb + ko)
                                    : (Ab + (size_t)(rowBase + r) * lda + ko);
            const uint32_t st = base + (isB ? A_FLOATS * 4 : 0) + r * (SROW * 4);
#pragma unroll
            for (int c = 0; c < 8; c++) CP16(st + c * 16, gsrc + c * 4);
        }
        // pass 2: B rows 128..255, half row per thread
        {
            const int r = 128 + (tid >> 1);
            const int h = (tid & 1) * 16;   // float offset within row
            const float* gsrc = Bb + (size_t)(colBase + r) * ldb + ko + h;
            const uint32_t st = base + A_FLOATS * 4 + r * (SROW * 4) + h * 4;
#pragma unroll
            for (int c = 0; c < 4; c++) CP16(st + c * 16, gsrc + c * 4);
        }
    };

    // fragment loader for one k8 step: 4 LDSM.x4 (A) + 4 LDSM.x4 (B)
    auto ldsm_ks = [&](uint32_t stA, uint32_t stB, int ks, uint32_t* fa, uint32_t* fb) {
        const uint32_t ko = (uint32_t)(ks * 8) * 4 + laneOff;
#pragma unroll
        for (int i = 0; i < 4; i++)
            LDSM4(fa[4 * i], fa[4 * i + 1], fa[4 * i + 2], fa[4 * i + 3],
                  stA + ko + (uint32_t)(i * 16) * (SROW * 4));
#pragma unroll
        for (int jp = 0; jp < 4; jp++)
            LDSM4(fb[4 * jp], fb[4 * jp + 1], fb[4 * jp + 2], fb[4 * jp + 3],
                  stB + ko + (uint32_t)(jp * 16) * (SROW * 4));
    };

    // ---- prologue ----
    load_stage(0, 0); CP_COMMIT();
    load_stage(1, 1); CP_COMMIT();

    uint32_t fa[2][16], fb[2][16];

    // ---- main loop ----
#pragma unroll 1
    for (int it = 0; it < niters; ++it) {
        const int s = it % STAGES;
        if (it < niters - 1) { CP_WAIT(1); } else { CP_WAIT(0); }
        __syncthreads();   // visibility of this stage's cp.async + ring reuse

        if (it + 2 < niters) { load_stage(it + 2, (it + 2) % STAGES); CP_COMMIT(); }

        const uint32_t stA = sbase + s * STAGE_BYTES
                           + (uint32_t)(wm * 64) * (SROW * 4);
        const uint32_t stB = sbase + s * STAGE_BYTES + A_FLOATS * 4
                           + (uint32_t)(wn * 64) * (SROW * 4);

        ldsm_ks(stA, stB, 0, fa[0], fb[0]);

#pragma unroll
        for (int ks = 0; ks < 4; ks++) {
            const int cur = ks & 1;
            if (ks < 3) ldsm_ks(stA, stB, ks + 1, fa[cur ^ 1], fb[cur ^ 1]);

            // round current buffer to tf32-nearest in place
#pragma unroll
            for (int q = 0; q < 16; q++) fa[cur][q] += 0x1000u;
#pragma unroll
            for (int q = 0; q < 16; q++) fb[cur][q] += 0x1000u;

#pragma unroll
            for (int i = 0; i < 4; i++)
#pragma unroll
                for (int j = 0; j < 8; j++) {
                    const int jp = j >> 1, jo = j & 1;
                    MMA_TF32(acc[i][j],
                             fa[cur][4 * i], fa[cur][4 * i + 1],
                             fa[cur][4 * i + 2], fa[cur][4 * i + 3],
                             fb[cur][4 * jp + jo], fb[cur][4 * jp + 2 + jo]);
                }
        }
    }

    // ---- epilogue: bias + ReLU, float2 stores ----
    float2 bv[8];
#pragma unroll
    for (int j = 0; j < 8; j++) {
        const int c = colBase + wn * 64 + j * 8 + 2 * tg;
        float2 b = *(const float2*)(bias1 + c);
        if (bias2) {
            float2 b2 = *(const float2*)(bias2 + c);
            b.x += b2.x; b.y += b2.y;
        }
        bv[j] = b;
    }
#pragma unroll
    for (int i = 0; i < 4; i++) {
        const int r0 = rowBase + wm * 64 + i * 16 + g;
#pragma unroll
        for (int j = 0; j < 8; j++) {
            const int c = colBase + wn * 64 + j * 8 + 2 * tg;
            float2 v0, v1;
            v0.x = fmaxf(acc[i][j][0] + bv[j].x, 0.0f);
            v0.y = fmaxf(acc[i][j][1] + bv[j].y, 0.0f);
            v1.x = fmaxf(acc[i][j][2] + bv[j].x, 0.0f);
            v1.y = fmaxf(acc[i][j][3] + bv[j].y, 0.0f);
            *(float2*)&C[(size_t)r0 * ldc + c]       = v0;
            *(float2*)&C[(size_t)(r0 + 8) * ldc + c] = v1;
        }
    }
}

extern "C" void kernel_launch(void* const* d_in, const int* in_sizes, int n_in,
                              void* d_out, int out_size)
{
    (void)in_sizes; (void)n_in; (void)out_size;
    const int B_ = 8192, DIN = 1024, H_ = 4096, DO_ = 1024;

    const float* X     = (const float*)d_in[0];
    const float* state = (const float*)d_in[1];
    const float* W_in  = (const float*)d_in[2];
    const float* b_in  = (const float*)d_in[3];
    const float* W_rec = (const float*)d_in[4];
    const float* b_rec = (const float*)d_in[5];
    const float* W_out = (const float*)d_in[6];
    const float* b_out = (const float*)d_in[7];

    float* out       = (float*)d_out;                     // [B, D_OUT]
    float* new_state = (float*)d_out + (size_t)B_ * DO_;  // [B, H]

    static int inited = 0;
    if (!inited) {
        cudaFuncSetAttribute(rnn_gemm_mma,
                             cudaFuncAttributeMaxDynamicSharedMemorySize, SMEM_BYTES);
        inited = 1;
    }

    // GEMM1+2 fused along K: new_state = ReLU(X@W_in^T + state@W_rec^T + b)
    {
        dim3 grid(H_ / BN, B_ / BM);   // (16, 64)
        rnn_gemm_mma<<<grid, 256, SMEM_BYTES>>>(
            X, DIN, W_in, DIN, DIN / BK,
            state, H_, W_rec, H_, H_ / BK,
            b_in, b_rec, new_state, H_);
    }
    // GEMM3: out = ReLU(new_state@W_out^T + b_out)
    {
        dim3 grid(DO_ / BN, B_ / BM);  // (4, 64)
        rnn_gemm_mma<<<grid, 256, SMEM_BYTES>>>(
            new_state, H_, W_out, H_, H_ / BK,
            nullptr, 0, nullptr, 0, 0,
            b_out, nullptr, out, DO_);
    }
}

// round 12
// speedup vs baseline: 2.2340x; 2.2340x over previous
#include <cuda_runtime.h>
#include <cuda_fp16.h>
#include <cstdint>

// VanillaRNN on GB300 — Round 11: fp16 datapath (mma.m16n8k16) + fp16 scratch.
//
//   new_state = ReLU(X@W_in^T + state@W_rec^T + b_in + b_rec)  [8192,4096]
//   out       = ReLU(new_state@W_out^T + b_out)                [8192,1024]
// d_out = (out, new_state) fp32. Inputs converted once per call to fp16 RN in
// __device__ scratch (fp16 has the same 11-bit significand as tf32 -> same
// error class, measured 4.17e-4 for tf32-RN). GEMM1+2 epilogue also writes
// new_state as fp16 for GEMM3.
//
// GEMM: BM=128, BN=256, BK=32, 256 thr (8 warps 2x4), warp tile 64x64.
// fp16 halves SMEM bytes and LDSM wavefronts; m16n8k16 halves MMA count at
// 2x FLOP each. 3-stage cp.async pipeline, stage 30KB. Fragments via
// ldmatrix.m8n8.x4.b16 (same verified mapping; 16B row segment = 8 halves).

#define BM 128
#define BN 256
#define BK 32
#define STAGES 3
#define SROWH 40                            // halves per smem row (32 + 8 pad) = 80B
#define A_HALVES (BM * SROWH)               // 5120
#define B_HALVES (BN * SROWH)               // 10240
#define STAGE_BYTES ((A_HALVES + B_HALVES) * 2)  // 30720
#define SMEM_BYTES  (STAGES * STAGE_BYTES)       // 92160

// ---- fp16 scratch (static device globals; allowed scratch mechanism) ----
__device__ __align__(16) __half g_hX[8192 * 1024];
__device__ __align__(16) __half g_hState[8192 * 4096];
__device__ __align__(16) __half g_hWin[4096 * 1024];
__device__ __align__(16) __half g_hWrec[4096 * 4096];
__device__ __align__(16) __half g_hWout[1024 * 4096];
__device__ __align__(16) __half g_hNew[8192 * 4096];

__device__ __forceinline__ uint32_t s2u(const void* p) {
    uint32_t a;
    asm("{ .reg .u64 t; cvta.to.shared.u64 t, %1; cvt.u32.u64 %0, t; }" : "=r"(a) : "l"(p));
    return a;
}

#define CP16(dst, src) \
    asm volatile("cp.async.cg.shared.global [%0], [%1], 16;" :: "r"(dst), "l"(src))
#define CP_COMMIT() asm volatile("cp.async.commit_group;" ::: "memory")
#define CP_WAIT(N)  asm volatile("cp.async.wait_group %0;" :: "n"(N) : "memory")

#define LDSM4(r0, r1, r2, r3, addr)                                            \
    asm volatile("ldmatrix.sync.aligned.m8n8.x4.shared.b16 {%0,%1,%2,%3}, [%4];" \
                 : "=r"(r0), "=r"(r1), "=r"(r2), "=r"(r3) : "r"(addr))

#define MMA_F16(ac, a0, a1, a2, a3, b0, b1)                                    \
    asm volatile(                                                              \
        "mma.sync.aligned.m16n8k16.row.col.f32.f16.f16.f32 "                   \
        "{%0,%1,%2,%3}, {%4,%5,%6,%7}, {%8,%9}, {%0,%1,%2,%3};"                \
        : "+f"((ac)[0]), "+f"((ac)[1]), "+f"((ac)[2]), "+f"((ac)[3])           \
        : "r"(a0), "r"(a1), "r"(a2), "r"(a3), "r"(b0), "r"(b1))

// ---- fp32 -> fp16 RN converter ----
__global__ void __launch_bounds__(256) f2h_kernel(const float4* __restrict__ src,
                                                  __half* __restrict__ dst, int n4)
{
    int i = blockIdx.x * blockDim.x + threadIdx.x;
    if (i < n4) {
        float4 v = src[i];
        __half2 h0 = __floats2half2_rn(v.x, v.y);
        __half2 h1 = __floats2half2_rn(v.z, v.w);
        uint2 pk;
        pk.x = *(uint32_t*)&h0;
        pk.y = *(uint32_t*)&h1;
        *(uint2*)(dst + 4 * (size_t)i) = pk;
    }
}

__global__ void __launch_bounds__(256) rnn_gemm_h(
    const __half* __restrict__ A1, int lda1,
    const __half* __restrict__ B1, int ldb1, int n1,
    const __half* __restrict__ A2, int lda2,
    const __half* __restrict__ B2, int ldb2, int n2,
    const float* __restrict__ bias1, const float* __restrict__ bias2,
    float* __restrict__ C, int ldc, __half* __restrict__ hC)
{
    extern __shared__ __align__(16) char smem[];
    const uint32_t sbase = s2u(smem);

    const int tid  = threadIdx.x;
    const int warp = tid >> 5;
    const int lane = tid & 31;
    const int tg   = lane & 3;
    const int g    = lane >> 2;
    const int wm   = warp >> 2;   // 0..1, rows wm*64..+64
    const int wn   = warp & 3;    // 0..3, cols wn*64..+64

    const int rowBase = blockIdx.y * BM;
    const int colBase = blockIdx.x * BN;
    const int niters  = n1 + n2;

    // ldmatrix lane offset (bytes): lanes 0-15 -> rows; lanes 16-31 -> +16B (k+8..15)
    const uint32_t laneOff = (uint32_t)(lane & 15) * (SROWH * 2) + ((lane >> 4) << 4);

    float acc[4][8][4];
#pragma unroll
    for (int i = 0; i < 4; i++)
#pragma unroll
        for (int j = 0; j < 8; j++)
#pragma unroll
            for (int v = 0; v < 4; v++) acc[i][j][v] = 0.0f;

    // ---- stage loader: 1536 16B chunks (A 512 + B 1024), 6 per thread ----
    auto load_stage = [&](int j, int s) {
        const __half* Ab; const __half* Bb; int lda, ldb, ko;
        if (j < n1) { Ab = A1; Bb = B1; lda = lda1; ldb = ldb1; ko = j * BK; }
        else        { Ab = A2; Bb = B2; lda = lda2; ldb = ldb2; ko = (j - n1) * BK; }
        const uint32_t base = sbase + s * STAGE_BYTES;
#pragma unroll
        for (int kk = 0; kk < 6; kk++) {
            const int c = tid + kk * 256;
            if (c < 512) {           // A chunk
                const int r  = c >> 2;
                const int ch = c & 3;
                CP16(base + r * (SROWH * 2) + ch * 16,
                     Ab + (size_t)(rowBase + r) * lda + ko + ch * 8);
            } else {                 // B chunk
                const int cb = c - 512;
                const int r  = cb >> 2;
                const int ch = cb & 3;
                CP16(base + A_HALVES * 2 + r * (SROWH * 2) + ch * 16,
                     Bb + (size_t)(colBase + r) * ldb + ko + ch * 8);
            }
        }
    };

    // ---- prologue ----
    load_stage(0, 0); CP_COMMIT();
    load_stage(1, 1); CP_COMMIT();

    // ---- main loop ----
#pragma unroll 1
    for (int it = 0; it < niters; ++it) {
        const int s = it % STAGES;
        if (it < niters - 1) { CP_WAIT(1); } else { CP_WAIT(0); }
        __syncthreads();   // stage visibility + ring reuse

        if (it + 2 < niters) { load_stage(it + 2, (it + 2) % STAGES); CP_COMMIT(); }

        const uint32_t stA = sbase + s * STAGE_BYTES
                           + (uint32_t)(wm * 64) * (SROWH * 2);
        const uint32_t stB = sbase + s * STAGE_BYTES + A_HALVES * 2
                           + (uint32_t)(wn * 64) * (SROWH * 2);

#pragma unroll
        for (int ks = 0; ks < 2; ks++) {        // two k16 steps per BK=32
            const uint32_t ko = (uint32_t)(ks * 32) + laneOff;  // 16 halves = 32B
            uint32_t fa[16], fb[16];
#pragma unroll
            for (int i = 0; i < 4; i++)
                LDSM4(fa[4 * i], fa[4 * i + 1], fa[4 * i + 2], fa[4 * i + 3],
                      stA + ko + (uint32_t)(i * 16) * (SROWH * 2));
#pragma unroll
            for (int jp = 0; jp < 4; jp++)
                LDSM4(fb[4 * jp], fb[4 * jp + 1], fb[4 * jp + 2], fb[4 * jp + 3],
                      stB + ko + (uint32_t)(jp * 16) * (SROWH * 2));

            // fa tile i: {r0,r1}=k0-7 rows m g/m g+8; {r2,r3}=k8-15  -> A frag order
            // fb LDSM jp: r0=n(2jp) k0-7, r1=n(2jp+1) k0-7, r2=n(2jp) k8-15, r3=...
#pragma unroll
            for (int i = 0; i < 4; i++)
#pragma unroll
                for (int j = 0; j < 8; j++) {
                    const int jp = j >> 1, jo = j & 1;
                    MMA_F16(acc[i][j],
                            fa[4 * i], fa[4 * i + 1], fa[4 * i + 2], fa[4 * i + 3],
                            fb[4 * jp + jo], fb[4 * jp + 2 + jo]);
                }
        }
    }

    // ---- epilogue: bias + ReLU; fp32 store (+ optional fp16 mirror) ----
    float2 bv[8];
#pragma unroll
    for (int j = 0; j < 8; j++) {
        const int c = colBase + wn * 64 + j * 8 + 2 * tg;
        float2 b = *(const float2*)(bias1 + c);
        if (bias2) {
            float2 b2 = *(const float2*)(bias2 + c);
            b.x += b2.x; b.y += b2.y;
        }
        bv[j] = b;
    }
#pragma unroll
    for (int i = 0; i < 4; i++) {
        const int r0 = rowBase + wm * 64 + i * 16 + g;
#pragma unroll
        for (int j = 0; j < 8; j++) {
            const int c = colBase + wn * 64 + j * 8 + 2 * tg;
            float2 v0, v1;
            v0.x = fmaxf(acc[i][j][0] + bv[j].x, 0.0f);
            v0.y = fmaxf(acc[i][j][1] + bv[j].y, 0.0f);
            v1.x = fmaxf(acc[i][j][2] + bv[j].x, 0.0f);
            v1.y = fmaxf(acc[i][j][3] + bv[j].y, 0.0f);
            *(float2*)&C[(size_t)r0 * ldc + c]       = v0;
            *(float2*)&C[(size_t)(r0 + 8) * ldc + c] = v1;
            if (hC) {
                __half2 h0 = __floats2half2_rn(v0.x, v0.y);
                __half2 h1 = __floats2half2_rn(v1.x, v1.y);
                *(__half2*)(hC + (size_t)r0 * ldc + c)       = h0;
                *(__half2*)(hC + (size_t)(r0 + 8) * ldc + c) = h1;
            }
        }
    }
}

// force eager module load (incl. 200MB device globals) before harness checkpoints
namespace {
struct EagerInit {
    EagerInit() { void* p = nullptr; cudaGetSymbolAddress(&p, g_hX); }
};
EagerInit s_eager;
}

extern "C" void kernel_launch(void* const* d_in, const int* in_sizes, int n_in,
                              void* d_out, int out_size)
{
    (void)in_sizes; (void)n_in; (void)out_size;
    const int B_ = 8192, DIN = 1024, H_ = 4096, DO_ = 1024;

    const float* X     = (const float*)d_in[0];
    const float* state = (const float*)d_in[1];
    const float* W_in  = (const float*)d_in[2];
    const float* b_in  = (const float*)d_in[3];
    const float* W_rec = (const float*)d_in[4];
    const float* b_rec = (const float*)d_in[5];
    const float* W_out = (const float*)d_in[6];
    const float* b_out = (const float*)d_in[7];

    float* out       = (float*)d_out;                     // [B, D_OUT]
    float* new_state = (float*)d_out + (size_t)B_ * DO_;  // [B, H]

    static __half *hX, *hState, *hWin, *hWrec, *hWout, *hNew;
    static int inited = 0;
    if (!inited) {
        cudaFuncSetAttribute(rnn_gemm_h,
                             cudaFuncAttributeMaxDynamicSharedMemorySize, SMEM_BYTES);
        cudaGetSymbolAddress((void**)&hX,     g_hX);
        cudaGetSymbolAddress((void**)&hState, g_hState);
        cudaGetSymbolAddress((void**)&hWin,   g_hWin);
        cudaGetSymbolAddress((void**)&hWrec,  g_hWrec);
        cudaGetSymbolAddress((void**)&hWout,  g_hWout);
        cudaGetSymbolAddress((void**)&hNew,   g_hNew);
        inited = 1;
    }

    // ---- fp32 -> fp16 conversions ----
    auto conv = [&](const float* src, __half* dst, size_t n) {
        int n4 = (int)(n / 4);
        f2h_kernel<<<(n4 + 255) / 256, 256>>>((const float4*)src, dst, n4);
    };
    conv(X,     hX,     (size_t)B_ * DIN);
    conv(state, hState, (size_t)B_ * H_);
    conv(W_in,  hWin,   (size_t)H_ * DIN);
    conv(W_rec, hWrec,  (size_t)H_ * H_);
    conv(W_out, hWout,  (size_t)DO_ * H_);

    // GEMM1+2 fused along K: new_state = ReLU(X@W_in^T + state@W_rec^T + b)
    {
        dim3 grid(H_ / BN, B_ / BM);   // (16, 64)
        rnn_gemm_h<<<grid, 256, SMEM_BYTES>>>(
            hX, DIN, hWin, DIN, DIN / BK,
            hState, H_, hWrec, H_, H_ / BK,
            b_in, b_rec, new_state, H_, hNew);
    }
    // GEMM3: out = ReLU(new_state@W_out^T + b_out)
    {
        dim3 grid(DO_ / BN, B_ / BM);  // (4, 64)
        rnn_gemm_h<<<grid, 256, SMEM_BYTES>>>(
            hNew, H_, hWout, H_, H_ / BK,
            nullptr, 0, nullptr, 0, 0,
            b_out, nullptr, out, DO_, nullptr);
    }
}

// round 13
// speedup vs baseline: 2.5025x; 1.1202x over previous
#include <cuda_runtime.h>
#include <cuda_fp16.h>
#include <cstdint>

// VanillaRNN on GB300 — Round 12: fp16 mma.m16n8k16, BK=64 (halve sync count).
//
//   new_state = ReLU(X@W_in^T + state@W_rec^T + b_in + b_rec)  [8192,4096]
//   out       = ReLU(new_state@W_out^T + b_out)                [8192,1024]
// d_out = (out, new_state) fp32. Inputs converted once per call to fp16 RN
// (same 11-bit significand as tf32; measured rel_err 4.16e-4). GEMM1 epilogue
// also writes new_state as fp16 for GEMM3.
//
// GEMM: BM=128, BN=256, BK=64, 256 thr (8 warps 2x4), warp tile 64x64.
// Per CTA-iter: 4 k16 steps = 512 warp-MMAs between barriers (2x R11).
// 3-stage cp.async pipeline, stage 54KB (1 CTA/SM). Fragments via
// ldmatrix.m8n8.x4.b16 (verified mapping; row stride 144B keeps the
// conflict-free bank pattern).

#define BM 128
#define BN 256
#define BK 64
#define STAGES 3
#define SROWH 72                            // halves per smem row (64 + 8 pad) = 144B
#define A_HALVES (BM * SROWH)               // 9216
#define B_HALVES (BN * SROWH)               // 18432
#define STAGE_BYTES ((A_HALVES + B_HALVES) * 2)  // 55296
#define SMEM_BYTES  (STAGES * STAGE_BYTES)       // 165888

// ---- fp16 scratch (static device globals; allowed scratch mechanism) ----
__device__ __align__(16) __half g_hX[8192 * 1024];
__device__ __align__(16) __half g_hState[8192 * 4096];
__device__ __align__(16) __half g_hWin[4096 * 1024];
__device__ __align__(16) __half g_hWrec[4096 * 4096];
__device__ __align__(16) __half g_hWout[1024 * 4096];
__device__ __align__(16) __half g_hNew[8192 * 4096];

__device__ __forceinline__ uint32_t s2u(const void* p) {
    uint32_t a;
    asm("{ .reg .u64 t; cvta.to.shared.u64 t, %1; cvt.u32.u64 %0, t; }" : "=r"(a) : "l"(p));
    return a;
}

#define CP16(dst, src) \
    asm volatile("cp.async.cg.shared.global [%0], [%1], 16;" :: "r"(dst), "l"(src))
#define CP_COMMIT() asm volatile("cp.async.commit_group;" ::: "memory")
#define CP_WAIT(N)  asm volatile("cp.async.wait_group %0;" :: "n"(N) : "memory")

#define LDSM4(r0, r1, r2, r3, addr)                                            \
    asm volatile("ldmatrix.sync.aligned.m8n8.x4.shared.b16 {%0,%1,%2,%3}, [%4];" \
                 : "=r"(r0), "=r"(r1), "=r"(r2), "=r"(r3) : "r"(addr))

#define MMA_F16(ac, a0, a1, a2, a3, b0, b1)                                    \
    asm volatile(                                                              \
        "mma.sync.aligned.m16n8k16.row.col.f32.f16.f16.f32 "                   \
        "{%0,%1,%2,%3}, {%4,%5,%6,%7}, {%8,%9}, {%0,%1,%2,%3};"                \
        : "+f"((ac)[0]), "+f"((ac)[1]), "+f"((ac)[2]), "+f"((ac)[3])           \
        : "r"(a0), "r"(a1), "r"(a2), "r"(a3), "r"(b0), "r"(b1))

// ---- fp32 -> fp16 RN converter ----
__global__ void __launch_bounds__(256) f2h_kernel(const float4* __restrict__ src,
                                                  __half* __restrict__ dst, int n4)
{
    int i = blockIdx.x * blockDim.x + threadIdx.x;
    if (i < n4) {
        float4 v = src[i];
        __half2 h0 = __floats2half2_rn(v.x, v.y);
        __half2 h1 = __floats2half2_rn(v.z, v.w);
        uint2 pk;
        pk.x = *(uint32_t*)&h0;
        pk.y = *(uint32_t*)&h1;
        *(uint2*)(dst + 4 * (size_t)i) = pk;
    }
}

__global__ void __launch_bounds__(256) rnn_gemm_h(
    const __half* __restrict__ A1, int lda1,
    const __half* __restrict__ B1, int ldb1, int n1,
    const __half* __restrict__ A2, int lda2,
    const __half* __restrict__ B2, int ldb2, int n2,
    const float* __restrict__ bias1, const float* __restrict__ bias2,
    float* __restrict__ C, int ldc, __half* __restrict__ hC)
{
    extern __shared__ __align__(16) char smem[];
    const uint32_t sbase = s2u(smem);

    const int tid  = threadIdx.x;
    const int warp = tid >> 5;
    const int lane = tid & 31;
    const int tg   = lane & 3;
    const int g    = lane >> 2;
    const int wm   = warp >> 2;   // 0..1, rows wm*64..+64
    const int wn   = warp & 3;    // 0..3, cols wn*64..+64

    const int rowBase = blockIdx.y * BM;
    const int colBase = blockIdx.x * BN;
    const int niters  = n1 + n2;

    // ldmatrix lane offset (bytes): lanes 0-15 -> rows; lanes 16-31 -> +16B (k+8..15)
    const uint32_t laneOff = (uint32_t)(lane & 15) * (SROWH * 2) + ((lane >> 4) << 4);

    float acc[4][8][4];
#pragma unroll
    for (int i = 0; i < 4; i++)
#pragma unroll
        for (int j = 0; j < 8; j++)
#pragma unroll
            for (int v = 0; v < 4; v++) acc[i][j][v] = 0.0f;

    // ---- stage loader: 3072 16B chunks (A 1024 + B 2048), 12 per thread ----
    auto load_stage = [&](int j, int s) {
        const __half* Ab; const __half* Bb; int lda, ldb, ko;
        if (j < n1) { Ab = A1; Bb = B1; lda = lda1; ldb = ldb1; ko = j * BK; }
        else        { Ab = A2; Bb = B2; lda = lda2; ldb = ldb2; ko = (j - n1) * BK; }
        const uint32_t base = sbase + s * STAGE_BYTES;
#pragma unroll
        for (int kk = 0; kk < 12; kk++) {
            const int c = tid + kk * 256;
            if (c < 1024) {          // A chunk: 128 rows x 8 chunks
                const int r  = c >> 3;
                const int ch = c & 7;
                CP16(base + r * (SROWH * 2) + ch * 16,
                     Ab + (size_t)(rowBase + r) * lda + ko + ch * 8);
            } else {                 // B chunk: 256 rows x 8 chunks
                const int cb = c - 1024;
                const int r  = cb >> 3;
                const int ch = cb & 7;
                CP16(base + A_HALVES * 2 + r * (SROWH * 2) + ch * 16,
                     Bb + (size_t)(colBase + r) * ldb + ko + ch * 8);
            }
        }
    };

    // ---- prologue ----
    load_stage(0, 0); CP_COMMIT();
    load_stage(1, 1); CP_COMMIT();

    // ---- main loop ----
#pragma unroll 1
    for (int it = 0; it < niters; ++it) {
        const int s = it % STAGES;
        if (it < niters - 1) { CP_WAIT(1); } else { CP_WAIT(0); }
        __syncthreads();   // stage visibility + ring reuse

        if (it + 2 < niters) { load_stage(it + 2, (it + 2) % STAGES); CP_COMMIT(); }

        const uint32_t stA = sbase + s * STAGE_BYTES
                           + (uint32_t)(wm * 64) * (SROWH * 2);
        const uint32_t stB = sbase + s * STAGE_BYTES + A_HALVES * 2
                           + (uint32_t)(wn * 64) * (SROWH * 2);

#pragma unroll
        for (int ks = 0; ks < 4; ks++) {        // four k16 steps per BK=64
            const uint32_t ko = (uint32_t)(ks * 32) + laneOff;  // 16 halves = 32B
            uint32_t fa[16], fb[16];
#pragma unroll
            for (int i = 0; i < 4; i++)
                LDSM4(fa[4 * i], fa[4 * i + 1], fa[4 * i + 2], fa[4 * i + 3],
                      stA + ko + (uint32_t)(i * 16) * (SROWH * 2));
#pragma unroll
            for (int jp = 0; jp < 4; jp++)
                LDSM4(fb[4 * jp], fb[4 * jp + 1], fb[4 * jp + 2], fb[4 * jp + 3],
                      stB + ko + (uint32_t)(jp * 16) * (SROWH * 2));

#pragma unroll
            for (int i = 0; i < 4; i++)
#pragma unroll
                for (int j = 0; j < 8; j++) {
                    const int jp = j >> 1, jo = j & 1;
                    MMA_F16(acc[i][j],
                            fa[4 * i], fa[4 * i + 1], fa[4 * i + 2], fa[4 * i + 3],
                            fb[4 * jp + jo], fb[4 * jp + 2 + jo]);
                }
        }
    }

    // ---- epilogue: bias + ReLU; fp32 store (+ optional fp16 mirror) ----
    float2 bv[8];
#pragma unroll
    for (int j = 0; j < 8; j++) {
        const int c = colBase + wn * 64 + j * 8 + 2 * tg;
        float2 b = *(const float2*)(bias1 + c);
        if (bias2) {
            float2 b2 = *(const float2*)(bias2 + c);
            b.x += b2.x; b.y += b2.y;
        }
        bv[j] = b;
    }
#pragma unroll
    for (int i = 0; i < 4; i++) {
        const int r0 = rowBase + wm * 64 + i * 16 + g;
#pragma unroll
        for (int j = 0; j < 8; j++) {
            const int c = colBase + wn * 64 + j * 8 + 2 * tg;
            float2 v0, v1;
            v0.x = fmaxf(acc[i][j][0] + bv[j].x, 0.0f);
            v0.y = fmaxf(acc[i][j][1] + bv[j].y, 0.0f);
            v1.x = fmaxf(acc[i][j][2] + bv[j].x, 0.0f);
            v1.y = fmaxf(acc[i][j][3] + bv[j].y, 0.0f);
            *(float2*)&C[(size_t)r0 * ldc + c]       = v0;
            *(float2*)&C[(size_t)(r0 + 8) * ldc + c] = v1;
            if (hC) {
                __half2 h0 = __floats2half2_rn(v0.x, v0.y);
                __half2 h1 = __floats2half2_rn(v1.x, v1.y);
                *(__half2*)(hC + (size_t)r0 * ldc + c)       = h0;
                *(__half2*)(hC + (size_t)(r0 + 8) * ldc + c) = h1;
            }
        }
    }
}

// force eager module load (incl. device globals) before harness checkpoints
namespace {
struct EagerInit {
    EagerInit() { void* p = nullptr; cudaGetSymbolAddress(&p, g_hX); }
};
EagerInit s_eager;
}

extern "C" void kernel_launch(void* const* d_in, const int* in_sizes, int n_in,
                              void* d_out, int out_size)
{
    (void)in_sizes; (void)n_in; (void)out_size;
    const int B_ = 8192, DIN = 1024, H_ = 4096, DO_ = 1024;

    const float* X     = (const float*)d_in[0];
    const float* state = (const float*)d_in[1];
    const float* W_in  = (const float*)d_in[2];
    const float* b_in  = (const float*)d_in[3];
    const float* W_rec = (const float*)d_in[4];
    const float* b_rec = (const float*)d_in[5];
    const float* W_out = (const float*)d_in[6];
    const float* b_out = (const float*)d_in[7];

    float* out       = (float*)d_out;                     // [B, D_OUT]
    float* new_state = (float*)d_out + (size_t)B_ * DO_;  // [B, H]

    static __half *hX, *hState, *hWin, *hWrec, *hWout, *hNew;
    static int inited = 0;
    if (!inited) {
        cudaFuncSetAttribute(rnn_gemm_h,
                             cudaFuncAttributeMaxDynamicSharedMemorySize, SMEM_BYTES);
        cudaGetSymbolAddress((void**)&hX,     g_hX);
        cudaGetSymbolAddress((void**)&hState, g_hState);
        cudaGetSymbolAddress((void**)&hWin,   g_hWin);
        cudaGetSymbolAddress((void**)&hWrec,  g_hWrec);
        cudaGetSymbolAddress((void**)&hWout,  g_hWout);
        cudaGetSymbolAddress((void**)&hNew,   g_hNew);
        inited = 1;
    }

    // ---- fp32 -> fp16 conversions ----
    auto conv = [&](const float* src, __half* dst, size_t n) {
        int n4 = (int)(n / 4);
        f2h_kernel<<<(n4 + 255) / 256, 256>>>((const float4*)src, dst, n4);
    };
    conv(X,     hX,     (size_t)B_ * DIN);
    conv(state, hState, (size_t)B_ * H_);
    conv(W_in,  hWin,   (size_t)H_ * DIN);
    conv(W_rec, hWrec,  (size_t)H_ * H_);
    conv(W_out, hWout,  (size_t)DO_ * H_);

    // GEMM1+2 fused along K: new_state = ReLU(X@W_in^T + state@W_rec^T + b)
    {
        dim3 grid(H_ / BN, B_ / BM);   // (16, 64)
        rnn_gemm_h<<<grid, 256, SMEM_BYTES>>>(
            hX, DIN, hWin, DIN, DIN / BK,
            hState, H_, hWrec, H_, H_ / BK,
            b_in, b_rec, new_state, H_, hNew);
    }
    // GEMM3: out = ReLU(new_state@W_out^T + b_out)
    {
        dim3 grid(DO_ / BN, B_ / BM);  // (4, 64)
        rnn_gemm_h<<<grid, 256, SMEM_BYTES>>>(
            hNew, H_, hWout, H_, H_ / BK,
            nullptr, 0, nullptr, 0, 0,
            b_out, nullptr, out, DO_, nullptr);
    }
}

// round 15
// speedup vs baseline: 2.6190x; 1.0466x over previous
#include <cuda_runtime.h>
#include <cuda_fp16.h>
#include <cstdint>

// VanillaRNN on GB300 — Round 13: 16 warps on the same 128x256x64 tile.
//
//   new_state = ReLU(X@W_in^T + state@W_rec^T + b_in + b_rec)  [8192,4096]
//   out       = ReLU(new_state@W_out^T + b_out)                [8192,1024]
// d_out = (out, new_state) fp32. Inputs converted once per call to fp16 RN.
// GEMM1 epilogue also writes new_state fp16 for GEMM3.
//
// GEMM: BM=128, BN=256, BK=64, 512 thr (16 warps, 4x4), warp tile 32x64.
// Same tile/stage/barrier structure as R12 (3-stage cp.async, 1 barrier/iter)
// but 4 warps per SMSP to hide LDSM/HMMA latency (R12 was 2/SMSP,
// latency-exposed). acc=64 regs/thread -> ~120 regs, no spill.

#define BM 128
#define BN 256
#define BK 64
#define STAGES 3
#define THREADS 512
#define SROWH 72                            // halves per smem row (64 + 8 pad) = 144B
#define A_HALVES (BM * SROWH)               // 9216
#define B_HALVES (BN * SROWH)               // 18432
#define STAGE_BYTES ((A_HALVES + B_HALVES) * 2)  // 55296
#define SMEM_BYTES  (STAGES * STAGE_BYTES)       // 165888

// ---- fp16 scratch (static device globals; allowed scratch mechanism) ----
__device__ __align__(16) __half g_hX[8192 * 1024];
__device__ __align__(16) __half g_hState[8192 * 4096];
__device__ __align__(16) __half g_hWin[4096 * 1024];
__device__ __align__(16) __half g_hWrec[4096 * 4096];
__device__ __align__(16) __half g_hWout[1024 * 4096];
__device__ __align__(16) __half g_hNew[8192 * 4096];

__device__ __forceinline__ uint32_t s2u(const void* p) {
    uint32_t a;
    asm("{ .reg .u64 t; cvta.to.shared.u64 t, %1; cvt.u32.u64 %0, t; }" : "=r"(a) : "l"(p));
    return a;
}

#define CP16(dst, src) \
    asm volatile("cp.async.cg.shared.global [%0], [%1], 16;" :: "r"(dst), "l"(src))
#define CP_COMMIT() asm volatile("cp.async.commit_group;" ::: "memory")
#define CP_WAIT(N)  asm volatile("cp.async.wait_group %0;" :: "n"(N) : "memory")

#define LDSM4(r0, r1, r2, r3, addr)                                            \
    asm volatile("ldmatrix.sync.aligned.m8n8.x4.shared.b16 {%0,%1,%2,%3}, [%4];" \
                 : "=r"(r0), "=r"(r1), "=r"(r2), "=r"(r3) : "r"(addr))

#define MMA_F16(ac, a0, a1, a2, a3, b0, b1)                                    \
    asm volatile(                                                              \
        "mma.sync.aligned.m16n8k16.row.col.f32.f16.f16.f32 "                   \
        "{%0,%1,%2,%3}, {%4,%5,%6,%7}, {%8,%9}, {%0,%1,%2,%3};"                \
        : "+f"((ac)[0]), "+f"((ac)[1]), "+f"((ac)[2]), "+f"((ac)[3])           \
        : "r"(a0), "r"(a1), "r"(a2), "r"(a3), "r"(b0), "r"(b1))

// ---- fp32 -> fp16 RN converter ----
__global__ void __launch_bounds__(256) f2h_kernel(const float4* __restrict__ src,
                                                  __half* __restrict__ dst, int n4)
{
    int i = blockIdx.x * blockDim.x + threadIdx.x;
    if (i < n4) {
        float4 v = src[i];
        __half2 h0 = __floats2half2_rn(v.x, v.y);
        __half2 h1 = __floats2half2_rn(v.z, v.w);
        uint2 pk;
        pk.x = *(uint32_t*)&h0;
        pk.y = *(uint32_t*)&h1;
        *(uint2*)(dst + 4 * (size_t)i) = pk;
    }
}

__global__ void __launch_bounds__(THREADS) rnn_gemm_h(
    const __half* __restrict__ A1, int lda1,
    const __half* __restrict__ B1, int ldb1, int n1,
    const __half* __restrict__ A2, int lda2,
    const __half* __restrict__ B2, int ldb2, int n2,
    const float* __restrict__ bias1, const float* __restrict__ bias2,
    float* __restrict__ C, int ldc, __half* __restrict__ hC)
{
    extern __shared__ __align__(16) char smem[];
    const uint32_t sbase = s2u(smem);

    const int tid  = threadIdx.x;
    const int warp = tid >> 5;
    const int lane = tid & 31;
    const int tg   = lane & 3;
    const int g    = lane >> 2;
    const int wm   = warp >> 2;   // 0..3, rows wm*32..+32
    const int wn   = warp & 3;    // 0..3, cols wn*64..+64

    const int rowBase = blockIdx.y * BM;
    const int colBase = blockIdx.x * BN;
    const int niters  = n1 + n2;

    // ldmatrix lane offset (bytes): lanes 0-15 -> rows; lanes 16-31 -> +16B (k+8..15)
    const uint32_t laneOff = (uint32_t)(lane & 15) * (SROWH * 2) + ((lane >> 4) << 4);

    float acc[2][8][4];
#pragma unroll
    for (int i = 0; i < 2; i++)
#pragma unroll
        for (int j = 0; j < 8; j++)
#pragma unroll
            for (int v = 0; v < 4; v++) acc[i][j][v] = 0.0f;

    // ---- stage loader: 3072 16B chunks (A 1024 + B 2048), 6 per thread ----
    auto load_stage = [&](int j, int s) {
        const __half* Ab; const __half* Bb; int lda, ldb, ko;
        if (j < n1) { Ab = A1; Bb = B1; lda = lda1; ldb = ldb1; ko = j * BK; }
        else        { Ab = A2; Bb = B2; lda = lda2; ldb = ldb2; ko = (j - n1) * BK; }
        const uint32_t base = sbase + s * STAGE_BYTES;
#pragma unroll
        for (int kk = 0; kk < 6; kk++) {
            const int c = tid + kk * THREADS;
            if (c < 1024) {          // A chunk: 128 rows x 8 chunks
                const int r  = c >> 3;
                const int ch = c & 7;
                CP16(base + r * (SROWH * 2) + ch * 16,
                     Ab + (size_t)(rowBase + r) * lda + ko + ch * 8);
            } else {                 // B chunk: 256 rows x 8 chunks
                const int cb = c - 1024;
                const int r  = cb >> 3;
                const int ch = cb & 7;
                CP16(base + A_HALVES * 2 + r * (SROWH * 2) + ch * 16,
                     Bb + (size_t)(colBase + r) * ldb + ko + ch * 8);
            }
        }
    };

    // ---- prologue ----
    load_stage(0, 0); CP_COMMIT();
    load_stage(1, 1); CP_COMMIT();

    // ---- main loop ----
#pragma unroll 1
    for (int it = 0; it < niters; ++it) {
        const int s = it % STAGES;
        if (it < niters - 1) { CP_WAIT(1); } else { CP_WAIT(0); }
        __syncthreads();   // stage visibility + ring reuse

        if (it + 2 < niters) { load_stage(it + 2, (it + 2) % STAGES); CP_COMMIT(); }

        const uint32_t stA = sbase + s * STAGE_BYTES
                           + (uint32_t)(wm * 32) * (SROWH * 2);
        const uint32_t stB = sbase + s * STAGE_BYTES + A_HALVES * 2
                           + (uint32_t)(wn * 64) * (SROWH * 2);

#pragma unroll
        for (int ks = 0; ks < 4; ks++) {        // four k16 steps per BK=64
            const uint32_t ko = (uint32_t)(ks * 32) + laneOff;  // 16 halves = 32B
            uint32_t fa[8], fb[16];
#pragma unroll
            for (int i = 0; i < 2; i++)
                LDSM4(fa[4 * i], fa[4 * i + 1], fa[4 * i + 2], fa[4 * i + 3],
                      stA + ko + (uint32_t)(i * 16) * (SROWH * 2));
#pragma unroll
            for (int jp = 0; jp < 4; jp++)
                LDSM4(fb[4 * jp], fb[4 * jp + 1], fb[4 * jp + 2], fb[4 * jp + 3],
                      stB + ko + (uint32_t)(jp * 16) * (SROWH * 2));

#pragma unroll
            for (int i = 0; i < 2; i++)
#pragma unroll
                for (int j = 0; j < 8; j++) {
                    const int jp = j >> 1, jo = j & 1;
                    MMA_F16(acc[i][j],
                            fa[4 * i], fa[4 * i + 1], fa[4 * i + 2], fa[4 * i + 3],
                            fb[4 * jp + jo], fb[4 * jp + 2 + jo]);
                }
        }
    }

    // ---- epilogue: bias + ReLU; fp32 store (+ optional fp16 mirror) ----
    float2 bv[8];
#pragma unroll
    for (int j = 0; j < 8; j++) {
        const int c = colBase + wn * 64 + j * 8 + 2 * tg;
        float2 b = *(const float2*)(bias1 + c);
        if (bias2) {
            float2 b2 = *(const float2*)(bias2 + c);
            b.x += b2.x; b.y += b2.y;
        }
        bv[j] = b;
    }
#pragma unroll
    for (int i = 0; i < 2; i++) {
        const int r0 = rowBase + wm * 32 + i * 16 + g;
#pragma unroll
        for (int j = 0; j < 8; j++) {
            const int c = colBase + wn * 64 + j * 8 + 2 * tg;
            float2 v0, v1;
            v0.x = fmaxf(acc[i][j][0] + bv[j].x, 0.0f);
            v0.y = fmaxf(acc[i][j][1] + bv[j].y, 0.0f);
            v1.x = fmaxf(acc[i][j][2] + bv[j].x, 0.0f);
            v1.y = fmaxf(acc[i][j][3] + bv[j].y, 0.0f);
            *(float2*)&C[(size_t)r0 * ldc + c]       = v0;
            *(float2*)&C[(size_t)(r0 + 8) * ldc + c] = v1;
            if (hC) {
                __half2 h0 = __floats2half2_rn(v0.x, v0.y);
                __half2 h1 = __floats2half2_rn(v1.x, v1.y);
                *(__half2*)(hC + (size_t)r0 * ldc + c)       = h0;
                *(__half2*)(hC + (size_t)(r0 + 8) * ldc + c) = h1;
            }
        }
    }
}

// force eager module load (incl. device globals) before harness checkpoints
namespace {
struct EagerInit {
    EagerInit() { void* p = nullptr; cudaGetSymbolAddress(&p, g_hX); }
};
EagerInit s_eager;
}

extern "C" void kernel_launch(void* const* d_in, const int* in_sizes, int n_in,
                              void* d_out, int out_size)
{
    (void)in_sizes; (void)n_in; (void)out_size;
    const int B_ = 8192, DIN = 1024, H_ = 4096, DO_ = 1024;

    const float* X     = (const float*)d_in[0];
    const float* state = (const float*)d_in[1];
    const float* W_in  = (const float*)d_in[2];
    const float* b_in  = (const float*)d_in[3];
    const float* W_rec = (const float*)d_in[4];
    const float* b_rec = (const float*)d_in[5];
    const float* W_out = (const float*)d_in[6];
    const float* b_out = (const float*)d_in[7];

    float* out       = (float*)d_out;                     // [B, D_OUT]
    float* new_state = (float*)d_out + (size_t)B_ * DO_;  // [B, H]

    static __half *hX, *hState, *hWin, *hWrec, *hWout, *hNew;
    static int inited = 0;
    if (!inited) {
        cudaFuncSetAttribute(rnn_gemm_h,
                             cudaFuncAttributeMaxDynamicSharedMemorySize, SMEM_BYTES);
        cudaGetSymbolAddress((void**)&hX,     g_hX);
        cudaGetSymbolAddress((void**)&hState, g_hState);
        cudaGetSymbolAddress((void**)&hWin,   g_hWin);
        cudaGetSymbolAddress((void**)&hWrec,  g_hWrec);
        cudaGetSymbolAddress((void**)&hWout,  g_hWout);
        cudaGetSymbolAddress((void**)&hNew,   g_hNew);
        inited = 1;
    }

    // ---- fp32 -> fp16 conversions ----
    auto conv = [&](const float* src, __half* dst, size_t n) {
        int n4 = (int)(n / 4);
        f2h_kernel<<<(n4 + 255) / 256, 256>>>((const float4*)src, dst, n4);
    };
    conv(X,     hX,     (size_t)B_ * DIN);
    conv(state, hState, (size_t)B_ * H_);
    conv(W_in,  hWin,   (size_t)H_ * DIN);
    conv(W_rec, hWrec,  (size_t)H_ * H_);
    conv(W_out, hWout,  (size_t)DO_ * H_);

    // GEMM1+2 fused along K: new_state = ReLU(X@W_in^T + state@W_rec^T + b)
    {
        dim3 grid(H_ / BN, B_ / BM);   // (16, 64)
        rnn_gemm_h<<<grid, THREADS, SMEM_BYTES>>>(
            hX, DIN, hWin, DIN, DIN / BK,
            hState, H_, hWrec, H_, H_ / BK,
            b_in, b_rec, new_state, H_, hNew);
    }
    // GEMM3: out = ReLU(new_state@W_out^T + b_out)
    {
        dim3 grid(DO_ / BN, B_ / BM);  // (4, 64)
        rnn_gemm_h<<<grid, THREADS, SMEM_BYTES>>>(
            hNew, H_, hWout, H_, H_ / BK,
            nullptr, 0, nullptr, 0, 0,
            b_out, nullptr, out, DO_, nullptr);
    }
}